// round 5
// baseline (speedup 1.0000x reference)
#include <cuda_runtime.h>
#include <cstdint>

#define NN 100000
#define D 128

// ---------------- scratch (no allocations allowed) ----------------
__device__ float g_A[(size_t)NN * D];   // agg / gcn-accumulator / reused
__device__ float g_H[(size_t)NN * D];   // h = x @ W_gcn / agg2
__device__ float g_X[(size_t)NN * D];   // x after down-stage / x2 after gcn
__device__ float g_cnt[NN];             // counts / degrees

// ---------------- scatter-mean accumulate: warp per edge ----------------
__global__ void scatter_accum_kernel(const float* __restrict__ feat,
                                     const int* __restrict__ src,
                                     const int* __restrict__ dst,
                                     float* __restrict__ agg,
                                     float* __restrict__ cnt,
                                     int nE) {
    int gtid = blockIdx.x * blockDim.x + threadIdx.x;
    int e = gtid >> 5;
    int lane = gtid & 31;
    if (e >= nE) return;
    int s = src[e];
    int d = dst[e];
    float4 v = ((const float4*)(feat + (size_t)s * D))[lane];
    float* p = agg + (size_t)d * D + lane * 4;
    atomicAdd(p + 0, v.x);
    atomicAdd(p + 1, v.y);
    atomicAdd(p + 2, v.z);
    atomicAdd(p + 3, v.w);
    if (lane == 0) atomicAdd(cnt + d, 1.0f);
}

// ---------------- in-degree counting (thread per edge) ----------------
__global__ void degree_kernel(const int* __restrict__ dst,
                              float* __restrict__ cnt, int nE) {
    int e = blockIdx.x * blockDim.x + threadIdx.x;
    if (e < nE) atomicAdd(cnt + dst[e], 1.0f);
}

// ---------------- GCN normalized scatter: warp per edge ----------------
__global__ void gcn_scatter_kernel(const float* __restrict__ h,
                                   const int* __restrict__ src,
                                   const int* __restrict__ dst,
                                   const float* __restrict__ cnt,
                                   float* __restrict__ acc,
                                   int nE) {
    int gtid = blockIdx.x * blockDim.x + threadIdx.x;
    int e = gtid >> 5;
    int lane = gtid & 31;
    if (e >= nE) return;
    int s = src[e];
    int d = dst[e];
    float norm = rsqrtf((cnt[s] + 1.0f) * (cnt[d] + 1.0f));
    float4 v = ((const float4*)(h + (size_t)s * D))[lane];
    float* p = acc + (size_t)d * D + lane * 4;
    atomicAdd(p + 0, v.x * norm);
    atomicAdd(p + 1, v.y * norm);
    atomicAdd(p + 2, v.z * norm);
    atomicAdd(p + 3, v.w * norm);
}

// ---------------- GCN epilogue: x2 = acc + h/deg + b ----------------
__global__ void gcn_finish_kernel(const float* __restrict__ acc,
                                  const float* __restrict__ h,
                                  const float* __restrict__ cnt,
                                  const float* __restrict__ bias,
                                  float* __restrict__ out) {
    int i = blockIdx.x * blockDim.x + threadIdx.x;   // float4 index
    if (i >= NN * (D / 4)) return;
    int row = i >> 5;
    int c4 = i & 31;
    float inv = 1.0f / (cnt[row] + 1.0f);
    float4 a = ((const float4*)acc)[i];
    float4 hh = ((const float4*)h)[i];
    float4 b = ((const float4*)bias)[c4];
    float4 o;
    o.x = a.x + hh.x * inv + b.x;
    o.y = a.y + hh.y * inv + b.y;
    o.z = a.z + hh.z * inv + b.z;
    o.w = a.w + hh.w * inv + b.w;
    ((float4*)out)[i] = o;
}

// ---------------- fused GEMM: out = f(resid + (A[/cnt]) @ W + bias) ----------------
// BM=64, BN=128, full K=128. 256 threads: thread (tx=tid&31, ty=tid>>5)
// computes rows ty*8..ty*8+7 x cols tx*4..tx*4+3.
template <bool MEAN, bool EPI>
__global__ void __launch_bounds__(256)
gemm128_kernel(const float* __restrict__ A, const float* __restrict__ cnt,
               const float* __restrict__ W, const float* __restrict__ bias,
               const float* __restrict__ resid, float* __restrict__ out, int n) {
    extern __shared__ float smem[];
    float* sW = smem;                 // 128 x 128
    float* sA = smem + 128 * 128;     // 64 x 132 (padded)
    const int SA_STRIDE = 132;

    int tid = threadIdx.x;
    int tx = tid & 31;
    int ty = tid >> 5;
    int row0 = blockIdx.x * 64;

    // load W (16384 floats = 4096 float4, 16 per thread)
#pragma unroll
    for (int v = 0; v < 16; ++v) {
        int idx = v * 256 + tid;          // float4 index
        int k = idx >> 5;
        int c4 = idx & 31;
        *((float4*)&sW[k * 128 + c4 * 4]) = ((const float4*)W)[idx];
    }
    // load A tile (2048 float4, 8 per thread), optional mean-divide
#pragma unroll
    for (int v = 0; v < 8; ++v) {
        int idx = v * 256 + tid;
        int r = idx >> 5;
        int c4 = idx & 31;
        int grow = row0 + r;
        float4 a = make_float4(0.f, 0.f, 0.f, 0.f);
        if (grow < n) {
            a = ((const float4*)(A + (size_t)grow * D))[c4];
            if (MEAN) {
                float inv = 1.0f / fmaxf(cnt[grow], 1.0f);
                a.x *= inv; a.y *= inv; a.z *= inv; a.w *= inv;
            }
        }
        *((float4*)&sA[r * SA_STRIDE + c4 * 4]) = a;
    }
    __syncthreads();

    float acc[8][4];
#pragma unroll
    for (int i = 0; i < 8; ++i)
#pragma unroll
        for (int j = 0; j < 4; ++j) acc[i][j] = 0.0f;

#pragma unroll 4
    for (int k = 0; k < 128; k += 4) {
        float4 w0 = *(const float4*)&sW[(k + 0) * 128 + tx * 4];
        float4 w1 = *(const float4*)&sW[(k + 1) * 128 + tx * 4];
        float4 w2 = *(const float4*)&sW[(k + 2) * 128 + tx * 4];
        float4 w3 = *(const float4*)&sW[(k + 3) * 128 + tx * 4];
#pragma unroll
        for (int i = 0; i < 8; ++i) {
            float4 a = *(const float4*)&sA[(ty * 8 + i) * SA_STRIDE + k];
            acc[i][0] = fmaf(a.x, w0.x, acc[i][0]);
            acc[i][1] = fmaf(a.x, w0.y, acc[i][1]);
            acc[i][2] = fmaf(a.x, w0.z, acc[i][2]);
            acc[i][3] = fmaf(a.x, w0.w, acc[i][3]);
            acc[i][0] = fmaf(a.y, w1.x, acc[i][0]);
            acc[i][1] = fmaf(a.y, w1.y, acc[i][1]);
            acc[i][2] = fmaf(a.y, w1.z, acc[i][2]);
            acc[i][3] = fmaf(a.y, w1.w, acc[i][3]);
            acc[i][0] = fmaf(a.z, w2.x, acc[i][0]);
            acc[i][1] = fmaf(a.z, w2.y, acc[i][1]);
            acc[i][2] = fmaf(a.z, w2.z, acc[i][2]);
            acc[i][3] = fmaf(a.z, w2.w, acc[i][3]);
            acc[i][0] = fmaf(a.w, w3.x, acc[i][0]);
            acc[i][1] = fmaf(a.w, w3.y, acc[i][1]);
            acc[i][2] = fmaf(a.w, w3.z, acc[i][2]);
            acc[i][3] = fmaf(a.w, w3.w, acc[i][3]);
        }
    }

    // epilogue
#pragma unroll
    for (int i = 0; i < 8; ++i) {
        int grow = row0 + ty * 8 + i;
        if (grow >= n) continue;
        float4 o;
        o.x = acc[i][0]; o.y = acc[i][1]; o.z = acc[i][2]; o.w = acc[i][3];
        if (EPI) {
            float4 r4 = ((const float4*)(resid + (size_t)grow * D))[tx];
            float4 b4 = ((const float4*)bias)[tx];
            o.x = fmaxf(o.x + r4.x + b4.x, 0.0f);
            o.y = fmaxf(o.y + r4.y + b4.y, 0.0f);
            o.z = fmaxf(o.z + r4.z + b4.z, 0.0f);
            o.w = fmaxf(o.w + r4.w + b4.w, 0.0f);
        }
        ((float4*)(out + (size_t)grow * D))[tx] = o;
    }
}

// ---------------- launch ----------------
extern "C" void kernel_launch(void* const* d_in, const int* in_sizes, int n_in,
                              void* d_out, int out_size) {
    const float* emb = (const float*)d_in[0];
    const float* Wd  = (const float*)d_in[1];
    const float* bd  = (const float*)d_in[2];
    const float* Wg  = (const float*)d_in[3];
    const float* bg  = (const float*)d_in[4];
    const float* Wu  = (const float*)d_in[5];
    const float* bu  = (const float*)d_in[6];
    const int* d2u = (const int*)d_in[7];
    const int* sl  = (const int*)d_in[8];
    const int* u2d = (const int*)d_in[9];
    int nE1 = in_sizes[7] / 2;   // 100000
    int nE2 = in_sizes[8] / 2;   // 600000
    int nE3 = in_sizes[9] / 2;   // 100000
    float* out = (float*)d_out;

    float *A, *H, *X, *C;
    cudaGetSymbolAddress((void**)&A, g_A);
    cudaGetSymbolAddress((void**)&H, g_H);
    cudaGetSymbolAddress((void**)&X, g_X);
    cudaGetSymbolAddress((void**)&C, g_cnt);

    const size_t featBytes = (size_t)NN * D * sizeof(float);
    const size_t smemBytes = (128 * 128 + 64 * 132) * sizeof(float);  // 99328
    cudaFuncSetAttribute(gemm128_kernel<true, true>,
                         cudaFuncAttributeMaxDynamicSharedMemorySize, (int)smemBytes);
    cudaFuncSetAttribute(gemm128_kernel<false, false>,
                         cudaFuncAttributeMaxDynamicSharedMemorySize, (int)smemBytes);

    const int gemmGrid = (NN + 63) / 64;

    // ---- stage 1: down2up mean aggregate + transform + residual relu ----
    cudaMemsetAsync(A, 0, featBytes, 0);
    cudaMemsetAsync(C, 0, NN * sizeof(float), 0);
    scatter_accum_kernel<<<(nE1 + 7) / 8, 256>>>(emb, d2u, d2u + nE1, A, C, nE1);
    gemm128_kernel<true, true><<<gemmGrid, 256, smemBytes>>>(A, C, Wd, bd, emb, X, NN);

    // ---- stage 2: GCN ----
    cudaMemsetAsync(C, 0, NN * sizeof(float), 0);
    degree_kernel<<<(nE2 + 255) / 256, 256>>>(sl + nE2, C, nE2);
    gemm128_kernel<false, false><<<gemmGrid, 256, smemBytes>>>(X, nullptr, Wg, nullptr,
                                                               nullptr, H, NN);
    cudaMemsetAsync(A, 0, featBytes, 0);
    gcn_scatter_kernel<<<(nE2 + 7) / 8, 256>>>(H, sl, sl + nE2, C, A, nE2);
    gcn_finish_kernel<<<(NN * (D / 4) + 255) / 256, 256>>>(A, H, C, bg, X);

    // ---- stage 3: up2down mean aggregate + transform + residual relu ----
    cudaMemsetAsync(H, 0, featBytes, 0);
    cudaMemsetAsync(C, 0, NN * sizeof(float), 0);
    scatter_accum_kernel<<<(nE3 + 7) / 8, 256>>>(X, u2d, u2d + nE3, H, C, nE3);
    gemm128_kernel<true, true><<<gemmGrid, 256, smemBytes>>>(H, C, Wu, bu, X, out, NN);
}